// round 15
// baseline (speedup 1.0000x reference)
#include <cuda_runtime.h>
#include <math.h>

// Problem constants (fixed by setup_inputs)
#define BQ     1024
#define NKEYS  100000
#define DDIM   512
#define HF     672      // H*F = 96*7
#define TOPK   16
#define SLAB_K 24       // per-slab candidate list (margin over TOPK vs tf32 noise)
#define CAND   32       // rescored candidate count (margin over TOPK)
#define MT     64       // queries per CTA tile
#define NT     64       // keys per inner tile
#define KC     32       // D-chunk staged in shared
#define NTILES ((NKEYS + NT - 1) / NT)          // 1563

// Two-pass decay-pruned scan:
// Pass 1: newest P1_TILES tiles (decay ~[0.078, 1]) -> candidates + bound.
// Pass 2: remaining tiles, per-tile skip when decay_max < bound (provably safe
//         since score = sim*decay, |sim| <= 1). Tiles are STRIDED across slabs
//         so the few non-pruned (newest) tiles land on different CTAs.
#define P1_TILES 160
#define P1_SLABS 40
#define P1_TPS   4                                // 40*4 = 160
#define P1_T0    (NTILES - P1_TILES)              // 1403
#define P2_SLABS 64
#define P2_TPS   ((P1_T0 + P2_SLABS - 1) / P2_SLABS)   // 22
#define TOT_SLABS (P2_SLABS + P1_SLABS)           // 104

// Scratch (device globals; no dynamic allocation allowed)
__device__ float  g_qn[BQ * DDIM];        // fp32 element-wise normalized queries
__device__ float  g_decay[NTILES * NT];   // fp32 0.995^age (rounded from double pow)
__device__ float  g_knrm[NTILES * NT];    // fp32 max(||k||, 1e-12)
__device__ float  g_scale[NTILES * NT];   // decay / knrm (fp32, for tf32 scan)
__device__ float  g_pval[BQ * TOT_SLABS * SLAB_K];
__device__ int    g_pidx[BQ * TOT_SLABS * SLAB_K];
__device__ float  g_Lq[BQ];
__device__ float  g_bound;
__device__ int    g_cand[BQ * CAND];
__device__ float  g_topv[BQ * TOPK];
__device__ int    g_topi[BQ * TOPK];

__device__ __forceinline__ unsigned f2tf32(float x) {
    unsigned r;
    asm("cvt.rna.tf32.f32 %0, %1;" : "=r"(r) : "f"(x));
    return r;
}

__device__ __forceinline__ void mma_tf32(float c[4], const unsigned a[4], const unsigned b[2]) {
    asm volatile(
        "mma.sync.aligned.m16n8k8.row.col.f32.tf32.tf32.f32 "
        "{%0,%1,%2,%3}, {%4,%5,%6,%7}, {%8,%9}, {%0,%1,%2,%3};"
        : "+f"(c[0]), "+f"(c[1]), "+f"(c[2]), "+f"(c[3])
        : "r"(a[0]), "r"(a[1]), "r"(a[2]), "r"(a[3]), "r"(b[0]), "r"(b[1]));
}

// ---------------------------------------------------------------------------
// Kernel A: L2-normalize queries (fp32 chain like the reference).
// ---------------------------------------------------------------------------
__global__ __launch_bounds__(128) void qnorm_kernel(const float* __restrict__ q) {
    const int b   = blockIdx.x;
    const int tid = threadIdx.x;
    const int lane = tid & 31, warp = tid >> 5;

    float4 v = reinterpret_cast<const float4*>(q + (size_t)b * DDIM)[tid];
    float ss = v.x * v.x + v.y * v.y + v.z * v.z + v.w * v.w;
    #pragma unroll
    for (int o = 16; o > 0; o >>= 1) ss += __shfl_xor_sync(0xffffffffu, ss, o);

    __shared__ float ws[4];
    if (lane == 0) ws[warp] = ss;
    __syncthreads();
    float tot = ws[0] + ws[1] + ws[2] + ws[3];
    float nrm = fmaxf(sqrtf(tot), 1e-12f);

    v.x /= nrm; v.y /= nrm; v.z /= nrm; v.w /= nrm;
    reinterpret_cast<float4*>(g_qn + (size_t)b * DDIM)[tid] = v;
}

// ---------------------------------------------------------------------------
// Kernel B: per-key decay, fp32 clamped norm, combined fp32 scan scale.
// Timestamp dtype probed (int64 vs int32) via element NKEYS/2-1.
// ---------------------------------------------------------------------------
__global__ __launch_bounds__(256) void kscale_kernel(const float* __restrict__ keys,
                                                     const void* __restrict__ ts,
                                                     const int* __restrict__ gstep) {
    const int n = blockIdx.x * 8 + (threadIdx.x >> 5);
    if (n >= NKEYS) return;
    const int lane = threadIdx.x & 31;

    const float4* row = reinterpret_cast<const float4*>(keys + (size_t)n * DDIM);
    float ss = 0.f;
    #pragma unroll
    for (int i = 0; i < 4; i++) {
        float4 v = row[lane + 32 * i];
        ss += v.x * v.x + v.y * v.y + v.z * v.z + v.w * v.w;
    }
    #pragma unroll
    for (int o = 16; o > 0; o >>= 1) ss += __shfl_xor_sync(0xffffffffu, ss, o);

    if (lane == 0) {
        long long probe = reinterpret_cast<const long long*>(ts)[NKEYS / 2 - 1];
        bool layout64 = (probe >= 0LL && probe <= 1000000LL);
        long long tsn = layout64 ? reinterpret_cast<const long long*>(ts)[n]
                                 : (long long)reinterpret_cast<const int*>(ts)[n];
        double age = (double)(gstep[0] - (int)tsn);
        float  dec = (float)pow(0.995, age);
        float  nrm = fmaxf(sqrtf(ss), 1e-12f);
        g_decay[n] = dec;
        g_knrm[n]  = nrm;
        g_scale[n] = dec / nrm;
    }
}

// ---------------------------------------------------------------------------
// Scan kernel: fused tf32 GEMM (64q x 64k tiles) + per-query slab top-SLAB_K.
// grid = (BQ/MT, n_slabs), block = 128 (4 warps, each 32x32).
// Tiles per slab: tt = tile_base + slab*slab_step + i*iter_step, i<iters,
// bounded by tile_limit.
// use_bound: per-tile skip when the tile's max decay < g_bound (safe because
// score = sim * decay with |sim| <= 1; bound carries 1e-3 >> tf32-noise margin).
// The K-chunk loop is software-pipelined: next chunk's gmem loads are issued
// into registers while the current chunk's MMAs run.
// ---------------------------------------------------------------------------
__global__ __launch_bounds__(128) void scan_kernel(const float* __restrict__ keys,
                                                   int tile_base, int slab_step,
                                                   int iter_step, int iters,
                                                   int tile_limit, int out_slab,
                                                   int use_bound) {
    __shared__ unsigned As[MT][36];
    __shared__ unsigned Bs[NT][36];
    __shared__ float sims[MT][NT + 1];
    __shared__ float s_sh[NT];
    __shared__ float topv[MT][SLAB_K];
    __shared__ int   topi[MT][SLAB_K];

    const int tid  = threadIdx.x;
    const int lane = tid & 31, warp = tid >> 5;
    const int mw = warp & 1, nw = warp >> 1;
    const int m0 = blockIdx.x * MT;
    const int slab = blockIdx.y;

    const float Lb = use_bound ? g_bound : -INFINITY;

    // per-thread staging coordinates (4 float4 each for A and B)
    const int srow[4] = { (tid + 0)   >> 3, (tid + 128) >> 3,
                          (tid + 256) >> 3, (tid + 384) >> 3 };
    const int scol = (tid & 7) << 2;

    for (int i = tid; i < MT * SLAB_K; i += 128) {
        (&topv[0][0])[i] = -INFINITY;
        (&topi[0][0])[i] = 0;
    }

    for (int it = 0; it < iters; ++it) {
        const int tt = tile_base + slab * slab_step + it * iter_step;
        if (tt >= tile_limit) break;
        const int n0 = tt * NT;
        if (use_bound) {
            // tile's newest (largest-decay) key; decay monotone in index
            int nlast = min(n0 + NT, NKEYS) - 1;
            if (g_decay[nlast] < Lb) continue;   // CTA-uniform skip
        }
        __syncthreads();   // previous insertion / sims / s_sh consumers done
        if (tid < NT) {
            int n = n0 + tid;
            s_sh[tid] = (n < NKEYS) ? g_scale[n] : 0.f;
        }

        float acc[2][4][4];
        #pragma unroll
        for (int mf = 0; mf < 2; mf++)
            #pragma unroll
            for (int nf = 0; nf < 4; nf++)
                #pragma unroll
                for (int r = 0; r < 4; r++) acc[mf][nf][r] = 0.f;

        // prefetch chunk 0 into registers
        float4 ra[4], rb[4];
        #pragma unroll
        for (int i = 0; i < 4; i++) {
            ra[i] = *reinterpret_cast<const float4*>(
                g_qn + (size_t)(m0 + srow[i]) * DDIM + scol);
            int n = n0 + srow[i];
            rb[i] = (n < NKEYS)
                  ? *reinterpret_cast<const float4*>(keys + (size_t)n * DDIM + scol)
                  : make_float4(0.f, 0.f, 0.f, 0.f);
        }

        for (int k0 = 0; k0 < DDIM; k0 += KC) {
            // store current chunk regs -> smem (tf32)
            #pragma unroll
            for (int i = 0; i < 4; i++) {
                As[srow[i]][scol + 0] = f2tf32(ra[i].x);
                As[srow[i]][scol + 1] = f2tf32(ra[i].y);
                As[srow[i]][scol + 2] = f2tf32(ra[i].z);
                As[srow[i]][scol + 3] = f2tf32(ra[i].w);
                Bs[srow[i]][scol + 0] = f2tf32(rb[i].x);
                Bs[srow[i]][scol + 1] = f2tf32(rb[i].y);
                Bs[srow[i]][scol + 2] = f2tf32(rb[i].z);
                Bs[srow[i]][scol + 3] = f2tf32(rb[i].w);
            }
            // prefetch next chunk (latency hidden behind the MMAs below)
            if (k0 + KC < DDIM) {
                #pragma unroll
                for (int i = 0; i < 4; i++) {
                    ra[i] = *reinterpret_cast<const float4*>(
                        g_qn + (size_t)(m0 + srow[i]) * DDIM + k0 + KC + scol);
                    int n = n0 + srow[i];
                    rb[i] = (n < NKEYS)
                          ? *reinterpret_cast<const float4*>(
                                keys + (size_t)n * DDIM + k0 + KC + scol)
                          : make_float4(0.f, 0.f, 0.f, 0.f);
                }
            }
            __syncthreads();   // smem staged for all warps

            const int r = lane >> 2, c = lane & 3;
            #pragma unroll
            for (int kk = 0; kk < KC; kk += 8) {
                unsigned a[2][4], b[4][2];
                #pragma unroll
                for (int mf = 0; mf < 2; mf++) {
                    int rr = mw * 32 + mf * 16 + r;
                    a[mf][0] = As[rr][kk + c];
                    a[mf][1] = As[rr + 8][kk + c];
                    a[mf][2] = As[rr][kk + c + 4];
                    a[mf][3] = As[rr + 8][kk + c + 4];
                }
                #pragma unroll
                for (int nf = 0; nf < 4; nf++) {
                    int nn = nw * 32 + nf * 8 + r;
                    b[nf][0] = Bs[nn][kk + c];
                    b[nf][1] = Bs[nn][kk + c + 4];
                }
                #pragma unroll
                for (int mf = 0; mf < 2; mf++)
                    #pragma unroll
                    for (int nf = 0; nf < 4; nf++)
                        mma_tf32(acc[mf][nf], a[mf], b[nf]);
            }
            __syncthreads();   // frag reads done before next chunk's store
        }

        // spill warp tiles to shared sims
        {
            const int r = lane >> 2, c2 = (lane & 3) * 2;
            #pragma unroll
            for (int mf = 0; mf < 2; mf++)
                #pragma unroll
                for (int nf = 0; nf < 4; nf++) {
                    int rr = mw * 32 + mf * 16 + r;
                    int cc = nw * 32 + nf * 8 + c2;
                    sims[rr][cc]         = acc[mf][nf][0];
                    sims[rr][cc + 1]     = acc[mf][nf][1];
                    sims[rr + 8][cc]     = acc[mf][nf][2];
                    sims[rr + 8][cc + 1] = acc[mf][nf][3];
                }
        }
        __syncthreads();

        // one thread per query: scan 64 keys, maintain sorted top-SLAB_K
        if (tid < MT) {
            const int q = tid;
            float kth = topv[q][SLAB_K - 1];
            for (int j = 0; j < NT; j++) {
                int n = n0 + j;
                if (n >= NKEYS) break;
                float v = sims[q][j] * s_sh[j];
                if (v > kth) {
                    int p = SLAB_K - 1;
                    while (p > 0 && topv[q][p - 1] < v) {
                        topv[q][p] = topv[q][p - 1];
                        topi[q][p] = topi[q][p - 1];
                        p--;
                    }
                    topv[q][p] = v;
                    topi[q][p] = n;
                    kth = topv[q][SLAB_K - 1];
                }
            }
        }
    }
    __syncthreads();

    for (int i = tid; i < MT * SLAB_K; i += 128) {
        int q = i / SLAB_K, k = i % SLAB_K;
        size_t o = ((size_t)(m0 + q) * TOT_SLABS + out_slab + slab) * SLAB_K + k;
        g_pval[o] = topv[q][k];
        g_pidx[o] = topi[q][k];
    }
}

// ---------------------------------------------------------------------------
// Bound kernel: L_q = max over pass-1 slabs of that slab's 16th value.
// (>=16 keys with score >= L_q exist, so the true 16th-best >= L_q.)
// ---------------------------------------------------------------------------
__global__ __launch_bounds__(32) void bound_kernel() {
    const int q = blockIdx.x;
    const int lane = threadIdx.x;
    float m = -INFINITY;
    for (int s = lane; s < P1_SLABS; s += 32) {
        float v = g_pval[((size_t)q * TOT_SLABS + P2_SLABS + s) * SLAB_K + (TOPK - 1)];
        m = fmaxf(m, v);
    }
    #pragma unroll
    for (int o = 16; o > 0; o >>= 1) m = fmaxf(m, __shfl_xor_sync(0xffffffffu, m, o));
    if (lane == 0) g_Lq[q] = m;
}

// Reduce L_q -> global bound (min over queries, minus safety margin >> tf32 noise)
__global__ __launch_bounds__(256) void bound_reduce_kernel() {
    const int tid = threadIdx.x;
    __shared__ float sm[256];
    float m = INFINITY;
    for (int i = tid; i < BQ; i += 256) m = fminf(m, g_Lq[i]);
    sm[tid] = m;
    __syncthreads();
    for (int s = 128; s > 0; s >>= 1) {
        if (tid < s) sm[tid] = fminf(sm[tid], sm[tid + s]);
        __syncthreads();
    }
    if (tid == 0) g_bound = sm[0] - 1e-3f;
}

// ---------------------------------------------------------------------------
// Kernel D: merge TOT_SLABS*SLAB_K candidates per query -> top-CAND indices
// (by tf32 score; exact rescoring follows). grid=BQ, block=256.
// ---------------------------------------------------------------------------
__global__ __launch_bounds__(256) void merge_kernel() {
    const int q   = blockIdx.x;
    const int tid = threadIdx.x;
    const int NC  = TOT_SLABS * SLAB_K;  // 2496

    __shared__ float v[TOT_SLABS * SLAB_K];
    __shared__ int   ix[TOT_SLABS * SLAB_K];
    __shared__ float rv[256];
    __shared__ int   rp[256];

    for (int i = tid; i < NC; i += 256) {
        v[i]  = g_pval[(size_t)q * NC + i];
        ix[i] = g_pidx[(size_t)q * NC + i];
    }
    __syncthreads();

    for (int k = 0; k < CAND; k++) {
        float best = -INFINITY;
        int bp = 0;
        for (int i = tid; i < NC; i += 256)
            if (v[i] > best) { best = v[i]; bp = i; }
        rv[tid] = best; rp[tid] = bp;
        __syncthreads();
        for (int s = 128; s > 0; s >>= 1) {
            if (tid < s && rv[tid + s] > rv[tid]) {
                rv[tid] = rv[tid + s];
                rp[tid] = rp[tid + s];
            }
            __syncthreads();
        }
        if (tid == 0) {
            g_cand[q * CAND + k] = ix[rp[0]];
            v[rp[0]] = -INFINITY;
        }
        __syncthreads();
    }
}

// ---------------------------------------------------------------------------
// Kernel R: rescore CAND candidates per query mimicking the reference chain:
// kn_i = fl32(k_i / nrm32); sim32 = fl32( sum64( qn_i * kn_i ) );
// score = sim32 * decay32. Ties broken by smaller key index (lax.top_k).
// grid=BQ, block=256 (8 warps).
// ---------------------------------------------------------------------------
__global__ __launch_bounds__(256) void rescore_kernel(const float* __restrict__ keys) {
    const int q    = blockIdx.x;
    const int tid  = threadIdx.x;
    const int lane = tid & 31, warp = tid >> 5;

    __shared__ float cv[CAND];
    __shared__ int   ci[CAND];

    const float4* qr = reinterpret_cast<const float4*>(g_qn + (size_t)q * DDIM);

    for (int c = warp; c < CAND; c += 8) {
        int n = g_cand[q * CAND + c];
        const float4* kr = reinterpret_cast<const float4*>(keys + (size_t)n * DDIM);
        const float nrm = g_knrm[n];
        double acc = 0.0;
        #pragma unroll
        for (int i = 0; i < 4; i++) {
            float4 a = qr[lane + 32 * i];
            float4 b = kr[lane + 32 * i];
            float bx = b.x / nrm, by = b.y / nrm, bz = b.z / nrm, bw = b.w / nrm;
            acc += (double)a.x * bx + (double)a.y * by
                 + (double)a.z * bz + (double)a.w * bw;
        }
        #pragma unroll
        for (int o = 16; o > 0; o >>= 1) acc += __shfl_xor_sync(0xffffffffu, acc, o);
        if (lane == 0) {
            float sim32 = (float)acc;
            cv[c] = sim32 * g_decay[n];
            ci[c] = n;
        }
    }
    __syncthreads();

    if (tid == 0) {
        float lv[CAND]; int li[CAND];
        #pragma unroll
        for (int c = 0; c < CAND; c++) { lv[c] = cv[c]; li[c] = ci[c]; }
        // insertion sort: descending value, ties -> smaller index first
        #pragma unroll
        for (int i = 1; i < CAND; i++) {
            float kv = lv[i]; int kn = li[i];
            int j = i - 1;
            while (j >= 0 && (lv[j] < kv || (lv[j] == kv && li[j] > kn))) {
                lv[j + 1] = lv[j]; li[j + 1] = li[j]; j--;
            }
            lv[j + 1] = kv; li[j + 1] = kn;
        }
        #pragma unroll
        for (int k = 0; k < TOPK; k++) {
            g_topv[q * TOPK + k] = lv[k];
            g_topi[q * TOPK + k] = li[k];
        }
    }
}

// ---------------------------------------------------------------------------
// Kernel E: softmax(temp=0.1) + mask(>=0) + renorm(+1e-8) + weighted gather.
// grid=BQ, block=224 (672/3).
// ---------------------------------------------------------------------------
__global__ __launch_bounds__(224) void agg_kernel(const float* __restrict__ values,
                                                  float* __restrict__ out) {
    const int q   = blockIdx.x;
    const int tid = threadIdx.x;

    __shared__ float w[TOPK];
    __shared__ int   id[TOPK];

    if (tid == 0) {
        float s[TOPK], e[TOPK];
        float m = g_topv[q * TOPK];  // sorted descending -> max first
        float den = 0.f;
        #pragma unroll
        for (int k = 0; k < TOPK; k++) {
            s[k] = g_topv[q * TOPK + k];
            e[k] = expf((s[k] - m) * 10.0f);   // /TEMPERATURE
            den += e[k];
        }
        float den2 = 0.f;
        #pragma unroll
        for (int k = 0; k < TOPK; k++) {
            float wk = e[k] / den;
            if (s[k] < 0.0f) wk = 0.f;          // mask: top_sims >= MIN_SIMILARITY
            e[k] = wk;
            den2 += wk;
        }
        float r = 1.0f / (den2 + 1e-8f);
        #pragma unroll
        for (int k = 0; k < TOPK; k++) {
            w[k]  = e[k] * r;
            id[k] = g_topi[q * TOPK + k];
        }
    }
    __syncthreads();

    for (int e = tid; e < HF; e += 224) {
        float acc = 0.f;
        #pragma unroll
        for (int k = 0; k < TOPK; k++)
            acc += w[k] * __ldg(values + (size_t)id[k] * HF + e);
        out[(size_t)q * HF + e] = acc;
    }
}

// ---------------------------------------------------------------------------
extern "C" void kernel_launch(void* const* d_in, const int* in_sizes, int n_in,
                              void* d_out, int out_size) {
    const float* query      = (const float*)d_in[0];
    const float* keys       = (const float*)d_in[1];
    const float* values     = (const float*)d_in[2];
    const void*  timestamps = d_in[3];
    const int*   gstep      = (const int*)d_in[4];
    float*       out        = (float*)d_out;

    qnorm_kernel<<<BQ, 128>>>(query);
    kscale_kernel<<<(NKEYS + 7) / 8, 256>>>(keys, timestamps, gstep);

    // Pass 1: newest P1_TILES tiles, contiguous per slab, no bound.
    dim3 g1(BQ / MT, P1_SLABS);
    scan_kernel<<<g1, 128>>>(keys, P1_T0, P1_TPS, 1, P1_TPS, NTILES, P2_SLABS, 0);

    // Bound from pass-1 candidates.
    bound_kernel<<<BQ, 32>>>();
    bound_reduce_kernel<<<1, 256>>>();

    // Pass 2: older tiles, STRIDED across slabs (tt = slab + i*P2_SLABS) so
    // any non-pruned (newest) tiles spread over distinct CTAs.
    dim3 g2(BQ / MT, P2_SLABS);
    scan_kernel<<<g2, 128>>>(keys, 0, 1, P2_SLABS, P2_TPS, P1_T0, 0, 1);

    merge_kernel<<<BQ, 256>>>();
    rescore_kernel<<<BQ, 256>>>(keys);
    agg_kernel<<<BQ, 224>>>(values, out);
}

// round 16
// speedup vs baseline: 2.4751x; 2.4751x over previous
#include <cuda_runtime.h>
#include <math.h>

// Problem constants (fixed by setup_inputs)
#define BQ     1024
#define NKEYS  100000
#define DDIM   512
#define HF     672      // H*F = 96*7
#define TOPK   16
#define SLAB_K 24       // per-slab candidate list (margin over TOPK vs tf32 noise)
#define CAND   32       // rescored candidate count (margin over TOPK)
#define MT     64       // queries per CTA tile
#define NT     64       // keys per inner tile
#define KC     32       // D-chunk staged in shared
#define NTILES ((NKEYS + NT - 1) / NT)          // 1563
#define MAXAGE 5000

// Two-pass decay-pruned scan:
// Pass 1: newest P1_TILES tiles (decay ~[0.078, 1]) -> candidates + bound.
// Pass 2: remaining tiles, per-tile skip when decay_max < bound (provably safe
//         since score = sim*decay, |sim| <= 1). Tiles are STRIDED across slabs
//         so the few non-pruned (newest) tiles land on different CTAs.
#define P1_TILES 160
#define P1_SLABS 40
#define P1_TPS   4                                // 40*4 = 160
#define P1_T0    (NTILES - P1_TILES)              // 1403
#define P2_SLABS 64
#define P2_TPS   ((P1_T0 + P2_SLABS - 1) / P2_SLABS)   // 22
#define TOT_SLABS (P2_SLABS + P1_SLABS)           // 104

// Scratch (device globals; no dynamic allocation allowed)
__device__ float  g_dtab[MAXAGE + 1];     // fp32 0.995^age table (from double pow)
__device__ float  g_qn[BQ * DDIM];        // fp32 element-wise normalized queries
__device__ float  g_decay[NTILES * NT];   // fp32 0.995^age per key
__device__ float  g_knrm[NTILES * NT];    // fp32 max(||k||, 1e-12)
__device__ float  g_scale[NTILES * NT];   // decay / knrm (fp32, for tf32 scan)
__device__ float  g_pval[BQ * TOT_SLABS * SLAB_K];
__device__ int    g_pidx[BQ * TOT_SLABS * SLAB_K];
__device__ float  g_Lq[BQ];
__device__ float  g_bound;
__device__ int    g_cand[BQ * CAND];
__device__ float  g_topv[BQ * TOPK];
__device__ int    g_topi[BQ * TOPK];

__device__ __forceinline__ unsigned f2tf32(float x) {
    unsigned r;
    asm("cvt.rna.tf32.f32 %0, %1;" : "=r"(r) : "f"(x));
    return r;
}

__device__ __forceinline__ void mma_tf32(float c[4], const unsigned a[4], const unsigned b[2]) {
    asm volatile(
        "mma.sync.aligned.m16n8k8.row.col.f32.tf32.tf32.f32 "
        "{%0,%1,%2,%3}, {%4,%5,%6,%7}, {%8,%9}, {%0,%1,%2,%3};"
        : "+f"(c[0]), "+f"(c[1]), "+f"(c[2]), "+f"(c[3])
        : "r"(a[0]), "r"(a[1]), "r"(a[2]), "r"(a[3]), "r"(b[0]), "r"(b[1]));
}

// Double-float (df64) compensated accumulation in pure fp32.
// All steps via _rn intrinsics: immune to fast-math reassociation.
// acc(hi,lo) += a*b, error ~2^-44 relative — below fp64 vs fl32 rounding needs.
__device__ __forceinline__ void df_acc(float& hi, float& lo, float a, float b) {
    float p  = __fmul_rn(a, b);
    float pe = __fmaf_rn(a, b, -p);           // exact product tail
    float s  = __fadd_rn(hi, p);
    float bb = __fsub_rn(s, hi);
    float er = __fadd_rn(__fsub_rn(hi, __fsub_rn(s, bb)),
                         __fsub_rn(p,  bb));  // exact sum tail (TwoSum)
    hi = s;
    lo = __fadd_rn(lo, __fadd_rn(er, pe));
}

// ---------------------------------------------------------------------------
// Kernel T: decay table. Only 5001 double-pow calls on the gutted FP64 pipe.
// Values bit-identical to the previous per-key pow(0.995, age).
// ---------------------------------------------------------------------------
__global__ __launch_bounds__(256) void dtab_kernel() {
    int i = blockIdx.x * 256 + threadIdx.x;
    if (i <= MAXAGE) g_dtab[i] = (float)pow(0.995, (double)i);
}

// ---------------------------------------------------------------------------
// Kernel A: L2-normalize queries (fp32 chain like the reference).
// ---------------------------------------------------------------------------
__global__ __launch_bounds__(128) void qnorm_kernel(const float* __restrict__ q) {
    const int b   = blockIdx.x;
    const int tid = threadIdx.x;
    const int lane = tid & 31, warp = tid >> 5;

    float4 v = reinterpret_cast<const float4*>(q + (size_t)b * DDIM)[tid];
    float ss = v.x * v.x + v.y * v.y + v.z * v.z + v.w * v.w;
    #pragma unroll
    for (int o = 16; o > 0; o >>= 1) ss += __shfl_xor_sync(0xffffffffu, ss, o);

    __shared__ float ws[4];
    if (lane == 0) ws[warp] = ss;
    __syncthreads();
    float tot = ws[0] + ws[1] + ws[2] + ws[3];
    float nrm = fmaxf(sqrtf(tot), 1e-12f);

    v.x /= nrm; v.y /= nrm; v.z /= nrm; v.w /= nrm;
    reinterpret_cast<float4*>(g_qn + (size_t)b * DDIM)[tid] = v;
}

// ---------------------------------------------------------------------------
// Kernel B: per-key decay (table lookup), fp32 clamped norm, scan scale.
// Timestamp dtype probed (int64 vs int32) via element NKEYS/2-1.
// ---------------------------------------------------------------------------
__global__ __launch_bounds__(256) void kscale_kernel(const float* __restrict__ keys,
                                                     const void* __restrict__ ts,
                                                     const int* __restrict__ gstep) {
    const int n = blockIdx.x * 8 + (threadIdx.x >> 5);
    if (n >= NKEYS) return;
    const int lane = threadIdx.x & 31;

    const float4* row = reinterpret_cast<const float4*>(keys + (size_t)n * DDIM);
    float ss = 0.f;
    #pragma unroll
    for (int i = 0; i < 4; i++) {
        float4 v = row[lane + 32 * i];
        ss += v.x * v.x + v.y * v.y + v.z * v.z + v.w * v.w;
    }
    #pragma unroll
    for (int o = 16; o > 0; o >>= 1) ss += __shfl_xor_sync(0xffffffffu, ss, o);

    if (lane == 0) {
        long long probe = reinterpret_cast<const long long*>(ts)[NKEYS / 2 - 1];
        bool layout64 = (probe >= 0LL && probe <= 1000000LL);
        long long tsn = layout64 ? reinterpret_cast<const long long*>(ts)[n]
                                 : (long long)reinterpret_cast<const int*>(ts)[n];
        int age = gstep[0] - (int)tsn;
        float dec;
        if (age >= 0 && age <= MAXAGE) dec = g_dtab[age];
        else dec = (float)pow(0.995, (double)age);   // cold fallback
        float nrm = fmaxf(sqrtf(ss), 1e-12f);
        g_decay[n] = dec;
        g_knrm[n]  = nrm;
        g_scale[n] = dec / nrm;
    }
}

// ---------------------------------------------------------------------------
// Scan kernel: fused tf32 GEMM (64q x 64k tiles) + per-query slab top-SLAB_K.
// grid = (BQ/MT, n_slabs), block = 128 (4 warps, each 32x32).
// Tiles per slab: tt = tile_base + slab*slab_step + i*iter_step, i<iters.
// use_bound: per-tile skip when the tile's max decay < g_bound (safe because
// score = sim * decay with |sim| <= 1; bound carries 1e-3 >> tf32-noise margin).
// K-chunk loop software-pipelined (register prefetch of the next chunk).
// ---------------------------------------------------------------------------
__global__ __launch_bounds__(128) void scan_kernel(const float* __restrict__ keys,
                                                   int tile_base, int slab_step,
                                                   int iter_step, int iters,
                                                   int tile_limit, int out_slab,
                                                   int use_bound) {
    __shared__ unsigned As[MT][36];
    __shared__ unsigned Bs[NT][36];
    __shared__ float sims[MT][NT + 1];
    __shared__ float s_sh[NT];
    __shared__ float topv[MT][SLAB_K];
    __shared__ int   topi[MT][SLAB_K];

    const int tid  = threadIdx.x;
    const int lane = tid & 31, warp = tid >> 5;
    const int mw = warp & 1, nw = warp >> 1;
    const int m0 = blockIdx.x * MT;
    const int slab = blockIdx.y;

    const float Lb = use_bound ? g_bound : -INFINITY;

    // per-thread staging coordinates (4 float4 each for A and B)
    const int srow[4] = { (tid + 0)   >> 3, (tid + 128) >> 3,
                          (tid + 256) >> 3, (tid + 384) >> 3 };
    const int scol = (tid & 7) << 2;

    for (int i = tid; i < MT * SLAB_K; i += 128) {
        (&topv[0][0])[i] = -INFINITY;
        (&topi[0][0])[i] = 0;
    }

    for (int it = 0; it < iters; ++it) {
        const int tt = tile_base + slab * slab_step + it * iter_step;
        if (tt >= tile_limit) break;
        const int n0 = tt * NT;
        if (use_bound) {
            int nlast = min(n0 + NT, NKEYS) - 1;
            if (g_decay[nlast] < Lb) continue;   // CTA-uniform skip
        }
        __syncthreads();   // previous insertion / sims / s_sh consumers done
        if (tid < NT) {
            int n = n0 + tid;
            s_sh[tid] = (n < NKEYS) ? g_scale[n] : 0.f;
        }

        float acc[2][4][4];
        #pragma unroll
        for (int mf = 0; mf < 2; mf++)
            #pragma unroll
            for (int nf = 0; nf < 4; nf++)
                #pragma unroll
                for (int r = 0; r < 4; r++) acc[mf][nf][r] = 0.f;

        // prefetch chunk 0 into registers
        float4 ra[4], rb[4];
        #pragma unroll
        for (int i = 0; i < 4; i++) {
            ra[i] = *reinterpret_cast<const float4*>(
                g_qn + (size_t)(m0 + srow[i]) * DDIM + scol);
            int n = n0 + srow[i];
            rb[i] = (n < NKEYS)
                  ? *reinterpret_cast<const float4*>(keys + (size_t)n * DDIM + scol)
                  : make_float4(0.f, 0.f, 0.f, 0.f);
        }

        for (int k0 = 0; k0 < DDIM; k0 += KC) {
            #pragma unroll
            for (int i = 0; i < 4; i++) {
                As[srow[i]][scol + 0] = f2tf32(ra[i].x);
                As[srow[i]][scol + 1] = f2tf32(ra[i].y);
                As[srow[i]][scol + 2] = f2tf32(ra[i].z);
                As[srow[i]][scol + 3] = f2tf32(ra[i].w);
                Bs[srow[i]][scol + 0] = f2tf32(rb[i].x);
                Bs[srow[i]][scol + 1] = f2tf32(rb[i].y);
                Bs[srow[i]][scol + 2] = f2tf32(rb[i].z);
                Bs[srow[i]][scol + 3] = f2tf32(rb[i].w);
            }
            if (k0 + KC < DDIM) {
                #pragma unroll
                for (int i = 0; i < 4; i++) {
                    ra[i] = *reinterpret_cast<const float4*>(
                        g_qn + (size_t)(m0 + srow[i]) * DDIM + k0 + KC + scol);
                    int n = n0 + srow[i];
                    rb[i] = (n < NKEYS)
                          ? *reinterpret_cast<const float4*>(
                                keys + (size_t)n * DDIM + k0 + KC + scol)
                          : make_float4(0.f, 0.f, 0.f, 0.f);
                }
            }
            __syncthreads();   // smem staged for all warps

            const int r = lane >> 2, c = lane & 3;
            #pragma unroll
            for (int kk = 0; kk < KC; kk += 8) {
                unsigned a[2][4], b[4][2];
                #pragma unroll
                for (int mf = 0; mf < 2; mf++) {
                    int rr = mw * 32 + mf * 16 + r;
                    a[mf][0] = As[rr][kk + c];
                    a[mf][1] = As[rr + 8][kk + c];
                    a[mf][2] = As[rr][kk + c + 4];
                    a[mf][3] = As[rr + 8][kk + c + 4];
                }
                #pragma unroll
                for (int nf = 0; nf < 4; nf++) {
                    int nn = nw * 32 + nf * 8 + r;
                    b[nf][0] = Bs[nn][kk + c];
                    b[nf][1] = Bs[nn][kk + c + 4];
                }
                #pragma unroll
                for (int mf = 0; mf < 2; mf++)
                    #pragma unroll
                    for (int nf = 0; nf < 4; nf++)
                        mma_tf32(acc[mf][nf], a[mf], b[nf]);
            }
            __syncthreads();   // frag reads done before next chunk's store
        }

        // spill warp tiles to shared sims
        {
            const int r = lane >> 2, c2 = (lane & 3) * 2;
            #pragma unroll
            for (int mf = 0; mf < 2; mf++)
                #pragma unroll
                for (int nf = 0; nf < 4; nf++) {
                    int rr = mw * 32 + mf * 16 + r;
                    int cc = nw * 32 + nf * 8 + c2;
                    sims[rr][cc]         = acc[mf][nf][0];
                    sims[rr][cc + 1]     = acc[mf][nf][1];
                    sims[rr + 8][cc]     = acc[mf][nf][2];
                    sims[rr + 8][cc + 1] = acc[mf][nf][3];
                }
        }
        __syncthreads();

        // one thread per query: scan 64 keys, maintain sorted top-SLAB_K
        if (tid < MT) {
            const int q = tid;
            float kth = topv[q][SLAB_K - 1];
            for (int j = 0; j < NT; j++) {
                int n = n0 + j;
                if (n >= NKEYS) break;
                float v = sims[q][j] * s_sh[j];
                if (v > kth) {
                    int p = SLAB_K - 1;
                    while (p > 0 && topv[q][p - 1] < v) {
                        topv[q][p] = topv[q][p - 1];
                        topi[q][p] = topi[q][p - 1];
                        p--;
                    }
                    topv[q][p] = v;
                    topi[q][p] = n;
                    kth = topv[q][SLAB_K - 1];
                }
            }
        }
    }
    __syncthreads();

    for (int i = tid; i < MT * SLAB_K; i += 128) {
        int q = i / SLAB_K, k = i % SLAB_K;
        size_t o = ((size_t)(m0 + q) * TOT_SLABS + out_slab + slab) * SLAB_K + k;
        g_pval[o] = topv[q][k];
        g_pidx[o] = topi[q][k];
    }
}

// ---------------------------------------------------------------------------
// Bound kernel: L_q = max over pass-1 slabs of that slab's 16th value.
// ---------------------------------------------------------------------------
__global__ __launch_bounds__(32) void bound_kernel() {
    const int q = blockIdx.x;
    const int lane = threadIdx.x;
    float m = -INFINITY;
    for (int s = lane; s < P1_SLABS; s += 32) {
        float v = g_pval[((size_t)q * TOT_SLABS + P2_SLABS + s) * SLAB_K + (TOPK - 1)];
        m = fmaxf(m, v);
    }
    #pragma unroll
    for (int o = 16; o > 0; o >>= 1) m = fmaxf(m, __shfl_xor_sync(0xffffffffu, m, o));
    if (lane == 0) g_Lq[q] = m;
}

__global__ __launch_bounds__(256) void bound_reduce_kernel() {
    const int tid = threadIdx.x;
    __shared__ float sm[256];
    float m = INFINITY;
    for (int i = tid; i < BQ; i += 256) m = fminf(m, g_Lq[i]);
    sm[tid] = m;
    __syncthreads();
    for (int s = 128; s > 0; s >>= 1) {
        if (tid < s) sm[tid] = fminf(sm[tid], sm[tid + s]);
        __syncthreads();
    }
    if (tid == 0) g_bound = sm[0] - 1e-3f;
}

// ---------------------------------------------------------------------------
// Kernel D: merge TOT_SLABS*SLAB_K candidates per query -> top-CAND indices.
// ---------------------------------------------------------------------------
__global__ __launch_bounds__(256) void merge_kernel() {
    const int q   = blockIdx.x;
    const int tid = threadIdx.x;
    const int NC  = TOT_SLABS * SLAB_K;  // 2496

    __shared__ float v[TOT_SLABS * SLAB_K];
    __shared__ int   ix[TOT_SLABS * SLAB_K];
    __shared__ float rv[256];
    __shared__ int   rp[256];

    for (int i = tid; i < NC; i += 256) {
        v[i]  = g_pval[(size_t)q * NC + i];
        ix[i] = g_pidx[(size_t)q * NC + i];
    }
    __syncthreads();

    for (int k = 0; k < CAND; k++) {
        float best = -INFINITY;
        int bp = 0;
        for (int i = tid; i < NC; i += 256)
            if (v[i] > best) { best = v[i]; bp = i; }
        rv[tid] = best; rp[tid] = bp;
        __syncthreads();
        for (int s = 128; s > 0; s >>= 1) {
            if (tid < s && rv[tid + s] > rv[tid]) {
                rv[tid] = rv[tid + s];
                rp[tid] = rp[tid + s];
            }
            __syncthreads();
        }
        if (tid == 0) {
            g_cand[q * CAND + k] = ix[rp[0]];
            v[rp[0]] = -INFINITY;
        }
        __syncthreads();
    }
}

// ---------------------------------------------------------------------------
// Kernel R: rescore CAND candidates per query with df64 (pure fp32) math:
// kn_i = fl32(k_i / nrm32)  [IEEE div];  sim32 = fl32( df64_sum(qn_i * kn_i) );
// score = sim32 * decay32. Ties broken by smaller key index (lax.top_k).
// No FP64 — sm_103a's FP64 pipe is ~8 DFMA/cyc chip-wide and was costing ~1.2ms.
// grid=BQ, block=256 (8 warps).
// ---------------------------------------------------------------------------
__global__ __launch_bounds__(256) void rescore_kernel(const float* __restrict__ keys) {
    const int q    = blockIdx.x;
    const int tid  = threadIdx.x;
    const int lane = tid & 31, warp = tid >> 5;

    __shared__ float cv[CAND];
    __shared__ int   ci[CAND];

    const float4* qr = reinterpret_cast<const float4*>(g_qn + (size_t)q * DDIM);

    for (int c = warp; c < CAND; c += 8) {
        int n = g_cand[q * CAND + c];
        const float4* kr = reinterpret_cast<const float4*>(keys + (size_t)n * DDIM);
        const float nrm = g_knrm[n];
        float hi = 0.f, lo = 0.f;
        #pragma unroll
        for (int i = 0; i < 4; i++) {
            float4 a = qr[lane + 32 * i];
            float4 b = kr[lane + 32 * i];
            df_acc(hi, lo, a.x, __fdiv_rn(b.x, nrm));
            df_acc(hi, lo, a.y, __fdiv_rn(b.y, nrm));
            df_acc(hi, lo, a.z, __fdiv_rn(b.z, nrm));
            df_acc(hi, lo, a.w, __fdiv_rn(b.w, nrm));
        }
        // df64 butterfly reduction across the warp
        #pragma unroll
        for (int o = 16; o > 0; o >>= 1) {
            float oh = __shfl_xor_sync(0xffffffffu, hi, o);
            float ol = __shfl_xor_sync(0xffffffffu, lo, o);
            float s  = __fadd_rn(hi, oh);
            float bb = __fsub_rn(s, hi);
            float er = __fadd_rn(__fsub_rn(hi, __fsub_rn(s, bb)),
                                 __fsub_rn(oh, bb));
            hi = s;
            lo = __fadd_rn(lo, __fadd_rn(ol, er));
        }
        if (lane == 0) {
            float sim32 = __fadd_rn(hi, lo);
            cv[c] = sim32 * g_decay[n];
            ci[c] = n;
        }
    }
    __syncthreads();

    if (tid == 0) {
        float lv[CAND]; int li[CAND];
        #pragma unroll
        for (int c = 0; c < CAND; c++) { lv[c] = cv[c]; li[c] = ci[c]; }
        // insertion sort: descending value, ties -> smaller index first
        #pragma unroll
        for (int i = 1; i < CAND; i++) {
            float kv = lv[i]; int kn = li[i];
            int j = i - 1;
            while (j >= 0 && (lv[j] < kv || (lv[j] == kv && li[j] > kn))) {
                lv[j + 1] = lv[j]; li[j + 1] = li[j]; j--;
            }
            lv[j + 1] = kv; li[j + 1] = kn;
        }
        #pragma unroll
        for (int k = 0; k < TOPK; k++) {
            g_topv[q * TOPK + k] = lv[k];
            g_topi[q * TOPK + k] = li[k];
        }
    }
}

// ---------------------------------------------------------------------------
// Kernel E: softmax(temp=0.1) + mask(>=0) + renorm(+1e-8) + weighted gather.
// ---------------------------------------------------------------------------
__global__ __launch_bounds__(224) void agg_kernel(const float* __restrict__ values,
                                                  float* __restrict__ out) {
    const int q   = blockIdx.x;
    const int tid = threadIdx.x;

    __shared__ float w[TOPK];
    __shared__ int   id[TOPK];

    if (tid == 0) {
        float s[TOPK], e[TOPK];
        float m = g_topv[q * TOPK];  // sorted descending -> max first
        float den = 0.f;
        #pragma unroll
        for (int k = 0; k < TOPK; k++) {
            s[k] = g_topv[q * TOPK + k];
            e[k] = expf((s[k] - m) * 10.0f);   // /TEMPERATURE
            den += e[k];
        }
        float den2 = 0.f;
        #pragma unroll
        for (int k = 0; k < TOPK; k++) {
            float wk = e[k] / den;
            if (s[k] < 0.0f) wk = 0.f;          // mask: top_sims >= MIN_SIMILARITY
            e[k] = wk;
            den2 += wk;
        }
        float r = 1.0f / (den2 + 1e-8f);
        #pragma unroll
        for (int k = 0; k < TOPK; k++) {
            w[k]  = e[k] * r;
            id[k] = g_topi[q * TOPK + k];
        }
    }
    __syncthreads();

    for (int e = tid; e < HF; e += 224) {
        float acc = 0.f;
        #pragma unroll
        for (int k = 0; k < TOPK; k++)
            acc += w[k] * __ldg(values + (size_t)id[k] * HF + e);
        out[(size_t)q * HF + e] = acc;
    }
}

// ---------------------------------------------------------------------------
extern "C" void kernel_launch(void* const* d_in, const int* in_sizes, int n_in,
                              void* d_out, int out_size) {
    const float* query      = (const float*)d_in[0];
    const float* keys       = (const float*)d_in[1];
    const float* values     = (const float*)d_in[2];
    const void*  timestamps = d_in[3];
    const int*   gstep      = (const int*)d_in[4];
    float*       out        = (float*)d_out;

    dtab_kernel<<<(MAXAGE + 256) / 256, 256>>>();
    qnorm_kernel<<<BQ, 128>>>(query);
    kscale_kernel<<<(NKEYS + 7) / 8, 256>>>(keys, timestamps, gstep);

    // Pass 1: newest P1_TILES tiles, contiguous per slab, no bound.
    dim3 g1(BQ / MT, P1_SLABS);
    scan_kernel<<<g1, 128>>>(keys, P1_T0, P1_TPS, 1, P1_TPS, NTILES, P2_SLABS, 0);

    // Bound from pass-1 candidates.
    bound_kernel<<<BQ, 32>>>();
    bound_reduce_kernel<<<1, 256>>>();

    // Pass 2: older tiles, STRIDED across slabs so any non-pruned (newest)
    // tiles spread over distinct CTAs.
    dim3 g2(BQ / MT, P2_SLABS);
    scan_kernel<<<g2, 128>>>(keys, 0, 1, P2_SLABS, P2_TPS, P1_T0, 0, 1);

    merge_kernel<<<BQ, 256>>>();
    rescore_kernel<<<BQ, 256>>>(keys);
    agg_kernel<<<BQ, 224>>>(values, out);
}